// round 6
// baseline (speedup 1.0000x reference)
#include <cuda_runtime.h>
#include <cuda_bf16.h>
#include <mma.h>
#include <stdint.h>
#include <math.h>

using namespace nvcuda;

// Problem constants
#define BATCH   64
#define NSEQ    196
#define CDIM    1024
#define NHEAD   32
#define HDIM    32
#define MROWS   12544            // BATCH*NSEQ
#define QKVN    3072             // 3*CDIM

// ---------------------------------------------------------------------------
// Static scratch (no cudaMalloc allowed)
// ---------------------------------------------------------------------------
__device__ float g_qkv[(size_t)MROWS * QKVN];       // [12544, 3072] fp32
__device__ __nv_bfloat16 g_xh[(size_t)MROWS * CDIM];
__device__ __nv_bfloat16 g_xl[(size_t)MROWS * CDIM];
__device__ __nv_bfloat16 g_wqh[(size_t)QKVN * CDIM];   // W_qkv^T [3072,1024]
__device__ __nv_bfloat16 g_wql[(size_t)QKVN * CDIM];
__device__ __nv_bfloat16 g_wph[(size_t)CDIM * CDIM];   // W_proj^T [1024,1024]
__device__ __nv_bfloat16 g_wpl[(size_t)CDIM * CDIM];
__device__ __nv_bfloat16 g_ath[(size_t)MROWS * CDIM];  // attention out hi
__device__ __nv_bfloat16 g_atl[(size_t)MROWS * CDIM];  // attention out lo

// ---------------------------------------------------------------------------
// helpers
// ---------------------------------------------------------------------------
__device__ __forceinline__ uint32_t smem_u32(const void* p) {
    uint32_t a;
    asm("{ .reg .u64 t; cvta.to.shared.u64 t, %1; cvt.u32.u64 %0, t; }"
        : "=r"(a) : "l"(p));
    return a;
}
__device__ __forceinline__ void cp16(uint32_t dst, const void* src) {
    asm volatile("cp.async.cg.shared.global [%0], [%1], 16;\n"
                 :: "r"(dst), "l"(src));
}

// ---------------------------------------------------------------------------
// bf16-split conversion kernels
// ---------------------------------------------------------------------------
__global__ __launch_bounds__(256) void split4_kernel(
    const float* __restrict__ in, __nv_bfloat16* __restrict__ hi,
    __nv_bfloat16* __restrict__ lo)
{
    const size_t i0 = ((size_t)blockIdx.x * 256 + threadIdx.x) * 4;
    const float4 v = *(const float4*)(in + i0);
    __nv_bfloat16 h0 = __float2bfloat16(v.x), h1 = __float2bfloat16(v.y);
    __nv_bfloat16 h2 = __float2bfloat16(v.z), h3 = __float2bfloat16(v.w);
    __nv_bfloat16 l0 = __float2bfloat16(v.x - __bfloat162float(h0));
    __nv_bfloat16 l1 = __float2bfloat16(v.y - __bfloat162float(h1));
    __nv_bfloat16 l2 = __float2bfloat16(v.z - __bfloat162float(h2));
    __nv_bfloat16 l3 = __float2bfloat16(v.w - __bfloat162float(h3));
    *(__nv_bfloat162*)(hi + i0)     = __nv_bfloat162(h0, h1);
    *(__nv_bfloat162*)(hi + i0 + 2) = __nv_bfloat162(h2, h3);
    *(__nv_bfloat162*)(lo + i0)     = __nv_bfloat162(l0, l1);
    *(__nv_bfloat162*)(lo + i0 + 2) = __nv_bfloat162(l2, l3);
}

// in: [K, N] fp32 row-major  ->  hi/lo: [N, K] bf16 row-major
__global__ __launch_bounds__(256) void transpose_split_kernel(
    const float* __restrict__ in, __nv_bfloat16* __restrict__ hi,
    __nv_bfloat16* __restrict__ lo, int K, int N)
{
    __shared__ float t[32][33];
    const int bx = blockIdx.x;   // tile over N
    const int by = blockIdx.y;   // tile over K
    const int x = bx * 32 + threadIdx.x;
    #pragma unroll
    for (int i = 0; i < 32; i += 8) {
        const int y = by * 32 + threadIdx.y + i;
        t[threadIdx.y + i][threadIdx.x] = in[(size_t)y * N + x];
    }
    __syncthreads();
    const int k = by * 32 + threadIdx.x;
    #pragma unroll
    for (int i = 0; i < 32; i += 8) {
        const int n = bx * 32 + threadIdx.y + i;
        const float v = t[threadIdx.x][threadIdx.y + i];
        const __nv_bfloat16 h = __float2bfloat16(v);
        hi[(size_t)n * K + k] = h;
        lo[(size_t)n * K + k] = __float2bfloat16(v - __bfloat162float(h));
    }
}

// ---------------------------------------------------------------------------
// HMMA bf16-split GEMM: C[M,N] = A*B^T (+bias).  (unchanged from round 5)
// ---------------------------------------------------------------------------
#define BK       32
#define LDA      40
#define MAT_T    (128 * LDA * 2)
#define STAGE_B  (4 * MAT_T)
#define GEMM_SMEM (2 * STAGE_B)
#define LDC      132

__global__ __launch_bounds__(128) void gemm_bf16x3(
    const __nv_bfloat16* __restrict__ Ah, const __nv_bfloat16* __restrict__ Al,
    const __nv_bfloat16* __restrict__ Bh, const __nv_bfloat16* __restrict__ Bl,
    float* __restrict__ C, const float* __restrict__ bias,
    int M, int N, int K)
{
    extern __shared__ char smem[];
    const uint32_t sb = smem_u32(smem);
    const int tid = threadIdx.x;
    const int wid = tid >> 5;
    const int lane = tid & 31;
    const int wm = wid >> 1;
    const int wn = wid & 1;
    const int m0 = blockIdx.y * 128;
    const int n0 = blockIdx.x * 128;
    const int NK = K / BK;

    uint32_t doff[4];
    size_t goffA[4], goffB[4];
    #pragma unroll
    for (int it = 0; it < 4; it++) {
        const int id  = it * 128 + tid;
        const int row = id >> 2;
        const int seg = (id & 3) * 16;
        doff[it]  = row * (LDA * 2) + seg;
        goffA[it] = ((size_t)(m0 + row) * K) * 2 + seg;
        goffB[it] = ((size_t)(n0 + row) * K) * 2 + seg;
    }

    auto load_stage = [&](int s, int kc) {
        const uint32_t base = sb + s * STAGE_B;
        const size_t kb = (size_t)kc * (BK * 2);
        #pragma unroll
        for (int it = 0; it < 4; it++) {
            cp16(base + 0 * MAT_T + doff[it], (const char*)Ah + goffA[it] + kb);
            cp16(base + 1 * MAT_T + doff[it], (const char*)Al + goffA[it] + kb);
            cp16(base + 2 * MAT_T + doff[it], (const char*)Bh + goffB[it] + kb);
            cp16(base + 3 * MAT_T + doff[it], (const char*)Bl + goffB[it] + kb);
        }
        asm volatile("cp.async.commit_group;" ::: "memory");
    };

    wmma::fragment<wmma::accumulator, 16, 16, 16, float> acc[4][4];
    #pragma unroll
    for (int i = 0; i < 4; i++)
        #pragma unroll
        for (int j = 0; j < 4; j++)
            wmma::fill_fragment(acc[i][j], 0.0f);

    load_stage(0, 0);
    load_stage(1, 1);

    for (int kt = 0; kt < NK; kt++) {
        asm volatile("cp.async.wait_group 1;" ::: "memory");
        __syncthreads();

        const char* stg = smem + (kt & 1) * STAGE_B;
        const __nv_bfloat16* Ash_h = (const __nv_bfloat16*)(stg);
        const __nv_bfloat16* Ash_l = (const __nv_bfloat16*)(stg + MAT_T);
        const __nv_bfloat16* Bsh_h = (const __nv_bfloat16*)(stg + 2 * MAT_T);
        const __nv_bfloat16* Bsh_l = (const __nv_bfloat16*)(stg + 3 * MAT_T);

        #pragma unroll
        for (int ks = 0; ks < BK; ks += 16) {
            wmma::fragment<wmma::matrix_a, 16, 16, 16, __nv_bfloat16, wmma::row_major> ah[4], al[4];
            #pragma unroll
            for (int i = 0; i < 4; i++) {
                const int r = wm * 64 + i * 16;
                wmma::load_matrix_sync(ah[i], Ash_h + r * LDA + ks, LDA);
                wmma::load_matrix_sync(al[i], Ash_l + r * LDA + ks, LDA);
            }
            #pragma unroll
            for (int j = 0; j < 4; j++) {
                wmma::fragment<wmma::matrix_b, 16, 16, 16, __nv_bfloat16, wmma::col_major> bh, bl;
                const int c = wn * 64 + j * 16;
                wmma::load_matrix_sync(bh, Bsh_h + c * LDA + ks, LDA);
                wmma::load_matrix_sync(bl, Bsh_l + c * LDA + ks, LDA);
                #pragma unroll
                for (int i = 0; i < 4; i++) {
                    wmma::mma_sync(acc[i][j], ah[i], bh, acc[i][j]);
                    wmma::mma_sync(acc[i][j], ah[i], bl, acc[i][j]);
                    wmma::mma_sync(acc[i][j], al[i], bh, acc[i][j]);
                }
            }
        }

        __syncthreads();
        if (kt + 2 < NK) load_stage(kt & 1, kt + 2);
        else asm volatile("cp.async.commit_group;" ::: "memory");
    }

    __syncthreads();
    float* Csh = (float*)smem;
    #pragma unroll
    for (int i = 0; i < 4; i++)
        #pragma unroll
        for (int j = 0; j < 4; j++)
            wmma::store_matrix_sync(
                Csh + (wm * 64 + i * 16) * LDC + wn * 64 + j * 16,
                acc[i][j], LDC, wmma::mem_row_major);
    __syncthreads();

    float4 bb = make_float4(0.f, 0.f, 0.f, 0.f);
    if (bias) bb = *(const float4*)(bias + n0 + lane * 4);
    #pragma unroll 4
    for (int i = 0; i < 32; i++) {
        const int r = wid * 32 + i;
        float4 v = *(const float4*)(Csh + r * LDC + lane * 4);
        v.x += bb.x; v.y += bb.y; v.z += bb.z; v.w += bb.w;
        *(float4*)(C + (size_t)(m0 + r) * N + n0 + lane * 4) = v;
    }
}

// ---------------------------------------------------------------------------
// Tensor-core attention: one CTA per (b,h), 4 warps, M padded to 256.
// Flash-style over 7 key-blocks of 32.  bf16-split everywhere (lo*lo dropped).
// Writes output directly as bf16 hi/lo for the proj GEMM.
// ---------------------------------------------------------------------------
#define MP    256
#define KBLK  32
#define NBLK  7            // ceil(196/32) -> 224 padded keys
#define LDQ   40           // bf16 leading dim (Q, K, V, P tiles)
#define LDS   36           // fp32 leading dim (S / O staging)

#define ATT_SMEM ( (2*MP*LDQ + 4*KBLK*LDQ + 2*MP*LDQ) * 2 /* bf16 */ \
                 + (MP*LDS + MP + 729) * 4 /* fp32 */ )

__global__ __launch_bounds__(128) void attention_tc(
    const float* __restrict__ qkv,   // [12544, 3072]
    const float* __restrict__ rpk,   // [729, 32]
    __nv_bfloat16* __restrict__ ath, // [12544, 1024]
    __nv_bfloat16* __restrict__ atl)
{
    extern __shared__ char sm[];
    __nv_bfloat16* Qh = (__nv_bfloat16*)sm;          // [MP][LDQ]
    __nv_bfloat16* Ql = Qh + MP * LDQ;
    __nv_bfloat16* Kh = Ql + MP * LDQ;               // [KBLK][LDQ]
    __nv_bfloat16* Kl = Kh + KBLK * LDQ;
    __nv_bfloat16* Vh = Kl + KBLK * LDQ;
    __nv_bfloat16* Vl = Vh + KBLK * LDQ;
    __nv_bfloat16* Ph = Vl + KBLK * LDQ;             // [MP][LDQ]
    __nv_bfloat16* Pl = Ph + MP * LDQ;
    float* S     = (float*)(Pl + MP * LDQ);          // [MP][LDS]
    float* denom = S + MP * LDS;                     // [MP]
    float* rsh   = denom + MP;                       // [729]

    const int h   = blockIdx.x;
    const int b   = blockIdx.y;
    const int tid = threadIdx.x;
    const int wid = tid >> 5;
    const int lane = tid & 31;
    const float scale = 0.17677669529663687f;
    const float* base = qkv + (size_t)b * NSEQ * QKVN + h * HDIM;

    // rpk column h, denom init
    for (int i = tid; i < 729; i += 128) rsh[i] = rpk[(size_t)i * HDIM + h];
    denom[tid] = 0.0f;
    denom[tid + 128] = 0.0f;

    // Q load: scale + split, pad rows >=196 with zeros
    for (int idx = tid; idx < MP * 8; idx += 128) {
        const int r  = idx >> 3;
        const int c4 = (idx & 7) * 4;
        float4 v = make_float4(0.f, 0.f, 0.f, 0.f);
        if (r < NSEQ) {
            v = *(const float4*)(base + (size_t)r * QKVN + c4);
            v.x *= scale; v.y *= scale; v.z *= scale; v.w *= scale;
        }
        __nv_bfloat16 h0 = __float2bfloat16(v.x), h1 = __float2bfloat16(v.y);
        __nv_bfloat16 h2 = __float2bfloat16(v.z), h3 = __float2bfloat16(v.w);
        __nv_bfloat16* qh = Qh + r * LDQ + c4;
        __nv_bfloat16* ql = Ql + r * LDQ + c4;
        qh[0] = h0; qh[1] = h1; qh[2] = h2; qh[3] = h3;
        ql[0] = __float2bfloat16(v.x - __bfloat162float(h0));
        ql[1] = __float2bfloat16(v.y - __bfloat162float(h1));
        ql[2] = __float2bfloat16(v.z - __bfloat162float(h2));
        ql[3] = __float2bfloat16(v.w - __bfloat162float(h3));
    }

    // per-thread row assignment (within own warp's 64-row slab)
    const int r0 = wid * 64 + lane * 2;
    int dyc[2];
    #pragma unroll
    for (int rr = 0; rr < 2; rr++) {
        const int rc = (r0 + rr < NSEQ) ? (r0 + rr) : 0;
        dyc[rr] = (rc / 14 + 13) * 27 + (rc % 14) + 13;
    }

    wmma::fragment<wmma::accumulator, 16, 16, 16, float> acc_o[4][2];
    #pragma unroll
    for (int i = 0; i < 4; i++)
        #pragma unroll
        for (int j = 0; j < 2; j++)
            wmma::fill_fragment(acc_o[i][j], 0.0f);

    for (int kb = 0; kb < NBLK; kb++) {
        __syncthreads();   // previous block's PV (all warps) done before K/V overwrite
        // K/V block load + split (32 rows x 32 cols, zero pad)
        for (int idx = tid; idx < KBLK * 8; idx += 128) {
            const int r  = idx >> 3;
            const int c4 = (idx & 7) * 4;
            const int jg = kb * KBLK + r;
            float4 kv = make_float4(0.f, 0.f, 0.f, 0.f);
            float4 vv = make_float4(0.f, 0.f, 0.f, 0.f);
            if (jg < NSEQ) {
                kv = *(const float4*)(base + (size_t)jg * QKVN + CDIM  + c4);
                vv = *(const float4*)(base + (size_t)jg * QKVN + 2*CDIM + c4);
            }
            __nv_bfloat16* kh = Kh + r * LDQ + c4;
            __nv_bfloat16* kl = Kl + r * LDQ + c4;
            __nv_bfloat16* vh = Vh + r * LDQ + c4;
            __nv_bfloat16* vl = Vl + r * LDQ + c4;
            const float kf[4] = {kv.x, kv.y, kv.z, kv.w};
            const float vf[4] = {vv.x, vv.y, vv.z, vv.w};
            #pragma unroll
            for (int u = 0; u < 4; u++) {
                __nv_bfloat16 khh = __float2bfloat16(kf[u]);
                __nv_bfloat16 vhh = __float2bfloat16(vf[u]);
                kh[u] = khh; kl[u] = __float2bfloat16(kf[u] - __bfloat162float(khh));
                vh[u] = vhh; vl[u] = __float2bfloat16(vf[u] - __bfloat162float(vhh));
            }
        }
        __syncthreads();

        // S = Qh*Kh^T + Qh*Kl^T + Ql*Kh^T   (warp slab: 64 rows x 32 keys)
        {
            wmma::fragment<wmma::accumulator, 16, 16, 16, float> acc_s[4][2];
            #pragma unroll
            for (int i = 0; i < 4; i++)
                #pragma unroll
                for (int j = 0; j < 2; j++)
                    wmma::fill_fragment(acc_s[i][j], 0.0f);

            #pragma unroll
            for (int ks = 0; ks < 32; ks += 16) {
                wmma::fragment<wmma::matrix_a, 16, 16, 16, __nv_bfloat16, wmma::row_major> qh[4], ql[4];
                #pragma unroll
                for (int i = 0; i < 4; i++) {
                    const int r = wid * 64 + i * 16;
                    wmma::load_matrix_sync(qh[i], Qh + r * LDQ + ks, LDQ);
                    wmma::load_matrix_sync(ql[i], Ql + r * LDQ + ks, LDQ);
                }
                #pragma unroll
                for (int j = 0; j < 2; j++) {
                    wmma::fragment<wmma::matrix_b, 16, 16, 16, __nv_bfloat16, wmma::col_major> kh, kl;
                    wmma::load_matrix_sync(kh, Kh + (j * 16) * LDQ + ks, LDQ);
                    wmma::load_matrix_sync(kl, Kl + (j * 16) * LDQ + ks, LDQ);
                    #pragma unroll
                    for (int i = 0; i < 4; i++) {
                        wmma::mma_sync(acc_s[i][j], qh[i], kh, acc_s[i][j]);
                        wmma::mma_sync(acc_s[i][j], qh[i], kl, acc_s[i][j]);
                        wmma::mma_sync(acc_s[i][j], ql[i], kh, acc_s[i][j]);
                    }
                }
            }
            #pragma unroll
            for (int i = 0; i < 4; i++)
                #pragma unroll
                for (int j = 0; j < 2; j++)
                    wmma::store_matrix_sync(
                        S + (wid * 64 + i * 16) * LDS + j * 16,
                        acc_s[i][j], LDS, wmma::mem_row_major);
        }
        __syncwarp();

        // exp + bias + split P (each thread: its own 2 rows x 32 keys)
        #pragma unroll
        for (int rr = 0; rr < 2; rr++) {
            const int r = r0 + rr;
            float dl = 0.0f;
            #pragma unroll 8
            for (int j = 0; j < KBLK; j++) {
                const int jg = kb * KBLK + j;
                float p = 0.0f;
                if (jg < NSEQ) {
                    const int yj = jg / 14;
                    const int bidx = dyc[rr] - (yj * 13 + jg);   // yj*27+xj = yj*13+jg
                    p = __expf(S[r * LDS + j] + rsh[bidx]);
                }
                dl += p;
                const __nv_bfloat16 ph = __float2bfloat16(p);
                Ph[r * LDQ + j] = ph;
                Pl[r * LDQ + j] = __float2bfloat16(p - __bfloat162float(ph));
            }
            denom[r] += dl;
        }
        __syncwarp();

        // O += Ph*Vh + Ph*Vl + Pl*Vh
        #pragma unroll
        for (int ks = 0; ks < 32; ks += 16) {
            wmma::fragment<wmma::matrix_a, 16, 16, 16, __nv_bfloat16, wmma::row_major> ph[4], pl[4];
            #pragma unroll
            for (int i = 0; i < 4; i++) {
                const int r = wid * 64 + i * 16;
                wmma::load_matrix_sync(ph[i], Ph + r * LDQ + ks, LDQ);
                wmma::load_matrix_sync(pl[i], Pl + r * LDQ + ks, LDQ);
            }
            #pragma unroll
            for (int j = 0; j < 2; j++) {
                wmma::fragment<wmma::matrix_b, 16, 16, 16, __nv_bfloat16, wmma::row_major> vh, vl;
                wmma::load_matrix_sync(vh, Vh + ks * LDQ + j * 16, LDQ);
                wmma::load_matrix_sync(vl, Vl + ks * LDQ + j * 16, LDQ);
                #pragma unroll
                for (int i = 0; i < 4; i++) {
                    wmma::mma_sync(acc_o[i][j], ph[i], vh, acc_o[i][j]);
                    wmma::mma_sync(acc_o[i][j], ph[i], vl, acc_o[i][j]);
                    wmma::mma_sync(acc_o[i][j], pl[i], vh, acc_o[i][j]);
                }
            }
        }
        __syncwarp();
    }

    // epilogue: O frags -> S smem -> normalize -> bf16 hi/lo global
    #pragma unroll
    for (int i = 0; i < 4; i++)
        #pragma unroll
        for (int j = 0; j < 2; j++)
            wmma::store_matrix_sync(
                S + (wid * 64 + i * 16) * LDS + j * 16,
                acc_o[i][j], LDS, wmma::mem_row_major);
    __syncwarp();

    #pragma unroll
    for (int rr = 0; rr < 2; rr++) {
        const int r = r0 + rr;
        if (r < NSEQ) {
            const float inv = 1.0f / denom[r];
            __nv_bfloat16* oh = ath + (size_t)(b * NSEQ + r) * CDIM + h * HDIM;
            __nv_bfloat16* ol = atl + (size_t)(b * NSEQ + r) * CDIM + h * HDIM;
            #pragma unroll
            for (int c = 0; c < HDIM; c += 2) {
                const float o0 = S[r * LDS + c]     * inv;
                const float o1 = S[r * LDS + c + 1] * inv;
                const __nv_bfloat16 h0 = __float2bfloat16(o0);
                const __nv_bfloat16 h1 = __float2bfloat16(o1);
                *(__nv_bfloat162*)(oh + c) = __nv_bfloat162(h0, h1);
                *(__nv_bfloat162*)(ol + c) = __nv_bfloat162(
                    __float2bfloat16(o0 - __bfloat162float(h0)),
                    __float2bfloat16(o1 - __bfloat162float(h1)));
            }
        }
    }
}

// ---------------------------------------------------------------------------
// Launch
// ---------------------------------------------------------------------------
extern "C" void kernel_launch(void* const* d_in, const int* in_sizes, int n_in,
                              void* d_out, int out_size)
{
    const float* x      = (const float*)d_in[0];
    const float* W_qkv  = (const float*)d_in[1];
    const float* W_proj = (const float*)d_in[2];
    const float* b_proj = (const float*)d_in[3];
    const float* rpk    = (const float*)d_in[4];
    float* out = (float*)d_out;

    float *qkv;
    __nv_bfloat16 *xh, *xl, *wqh, *wql, *wph, *wpl, *ath, *atl;
    cudaGetSymbolAddress((void**)&qkv, g_qkv);
    cudaGetSymbolAddress((void**)&xh,  g_xh);
    cudaGetSymbolAddress((void**)&xl,  g_xl);
    cudaGetSymbolAddress((void**)&wqh, g_wqh);
    cudaGetSymbolAddress((void**)&wql, g_wql);
    cudaGetSymbolAddress((void**)&wph, g_wph);
    cudaGetSymbolAddress((void**)&wpl, g_wpl);
    cudaGetSymbolAddress((void**)&ath, g_ath);
    cudaGetSymbolAddress((void**)&atl, g_atl);

    cudaFuncSetAttribute(gemm_bf16x3,
                         cudaFuncAttributeMaxDynamicSharedMemorySize, GEMM_SMEM);
    cudaFuncSetAttribute(attention_tc,
                         cudaFuncAttributeMaxDynamicSharedMemorySize, ATT_SMEM);

    // 0) conversions
    split4_kernel<<<MROWS * CDIM / 1024, 256>>>(x, xh, xl);
    transpose_split_kernel<<<dim3(QKVN / 32, CDIM / 32), dim3(32, 8)>>>(
        W_qkv, wqh, wql, CDIM, QKVN);
    transpose_split_kernel<<<dim3(CDIM / 32, CDIM / 32), dim3(32, 8)>>>(
        W_proj, wph, wpl, CDIM, CDIM);

    // 1) QKV projection: [12544,1024] x [1024,3072]
    gemm_bf16x3<<<dim3(QKVN / 128, MROWS / 128), 128, GEMM_SMEM>>>(
        xh, xl, wqh, wql, qkv, nullptr, MROWS, QKVN, CDIM);

    // 2) tensor-core attention per (b,h); writes bf16 hi/lo directly
    attention_tc<<<dim3(NHEAD, BATCH), 128, ATT_SMEM>>>(qkv, rpk, ath, atl);

    // 3) output projection: [12544,1024] x [1024,1024] + bias
    gemm_bf16x3<<<dim3(CDIM / 128, MROWS / 128), 128, GEMM_SMEM>>>(
        ath, atl, wph, wpl, out, b_proj, MROWS, CDIM, CDIM);
}

// round 7
// speedup vs baseline: 1.4091x; 1.4091x over previous
#include <cuda_runtime.h>
#include <cuda_bf16.h>
#include <mma.h>
#include <stdint.h>
#include <math.h>

using namespace nvcuda;

// Problem constants
#define BATCH   64
#define NSEQ    196
#define CDIM    1024
#define NHEAD   32
#define HDIM    32
#define MROWS   12544            // BATCH*NSEQ
#define QKVN    3072             // 3*CDIM

// ---------------------------------------------------------------------------
// Static scratch (no cudaMalloc allowed)
// ---------------------------------------------------------------------------
__device__ float g_qkv[(size_t)MROWS * QKVN];       // [12544, 3072] fp32
__device__ __nv_bfloat16 g_xh[(size_t)MROWS * CDIM];
__device__ __nv_bfloat16 g_xl[(size_t)MROWS * CDIM];
__device__ __nv_bfloat16 g_wqh[(size_t)QKVN * CDIM];   // W_qkv^T [3072,1024]
__device__ __nv_bfloat16 g_wql[(size_t)QKVN * CDIM];
__device__ __nv_bfloat16 g_wph[(size_t)CDIM * CDIM];   // W_proj^T [1024,1024]
__device__ __nv_bfloat16 g_wpl[(size_t)CDIM * CDIM];
__device__ __nv_bfloat16 g_ath[(size_t)MROWS * CDIM];  // attention out hi
__device__ __nv_bfloat16 g_atl[(size_t)MROWS * CDIM];  // attention out lo

// ---------------------------------------------------------------------------
// helpers
// ---------------------------------------------------------------------------
__device__ __forceinline__ uint32_t smem_u32(const void* p) {
    uint32_t a;
    asm("{ .reg .u64 t; cvta.to.shared.u64 t, %1; cvt.u32.u64 %0, t; }"
        : "=r"(a) : "l"(p));
    return a;
}
__device__ __forceinline__ void cp16(uint32_t dst, const void* src) {
    asm volatile("cp.async.cg.shared.global [%0], [%1], 16;\n"
                 :: "r"(dst), "l"(src));
}

// ---------------------------------------------------------------------------
// bf16-split conversion kernels
// ---------------------------------------------------------------------------
__global__ __launch_bounds__(256) void split4_kernel(
    const float* __restrict__ in, __nv_bfloat16* __restrict__ hi,
    __nv_bfloat16* __restrict__ lo)
{
    const size_t i0 = ((size_t)blockIdx.x * 256 + threadIdx.x) * 4;
    const float4 v = *(const float4*)(in + i0);
    __nv_bfloat16 h0 = __float2bfloat16(v.x), h1 = __float2bfloat16(v.y);
    __nv_bfloat16 h2 = __float2bfloat16(v.z), h3 = __float2bfloat16(v.w);
    __nv_bfloat16 l0 = __float2bfloat16(v.x - __bfloat162float(h0));
    __nv_bfloat16 l1 = __float2bfloat16(v.y - __bfloat162float(h1));
    __nv_bfloat16 l2 = __float2bfloat16(v.z - __bfloat162float(h2));
    __nv_bfloat16 l3 = __float2bfloat16(v.w - __bfloat162float(h3));
    *(__nv_bfloat162*)(hi + i0)     = __nv_bfloat162(h0, h1);
    *(__nv_bfloat162*)(hi + i0 + 2) = __nv_bfloat162(h2, h3);
    *(__nv_bfloat162*)(lo + i0)     = __nv_bfloat162(l0, l1);
    *(__nv_bfloat162*)(lo + i0 + 2) = __nv_bfloat162(l2, l3);
}

// in: [K, N] fp32 row-major  ->  hi/lo: [N, K] bf16 row-major
__global__ __launch_bounds__(256) void transpose_split_kernel(
    const float* __restrict__ in, __nv_bfloat16* __restrict__ hi,
    __nv_bfloat16* __restrict__ lo, int K, int N)
{
    __shared__ float t[32][33];
    const int bx = blockIdx.x;   // tile over N
    const int by = blockIdx.y;   // tile over K
    const int x = bx * 32 + threadIdx.x;
    #pragma unroll
    for (int i = 0; i < 32; i += 8) {
        const int y = by * 32 + threadIdx.y + i;
        t[threadIdx.y + i][threadIdx.x] = in[(size_t)y * N + x];
    }
    __syncthreads();
    const int k = by * 32 + threadIdx.x;
    #pragma unroll
    for (int i = 0; i < 32; i += 8) {
        const int n = bx * 32 + threadIdx.y + i;
        const float v = t[threadIdx.x][threadIdx.y + i];
        const __nv_bfloat16 h = __float2bfloat16(v);
        hi[(size_t)n * K + k] = h;
        lo[(size_t)n * K + k] = __float2bfloat16(v - __bfloat162float(h));
    }
}

// ---------------------------------------------------------------------------
// HMMA bf16-split GEMM: C[M,N] = A*B^T (+bias).
// 128x128 CTA tile, BK=32, 4 warps (2x2), warp tile 64x64.
// bias==nullptr: accumulators stored directly to global (no smem epilogue).
// bias!=nullptr: smem round-trip epilogue with coalesced bias-add stores.
// ---------------------------------------------------------------------------
#define BK       32
#define LDA      40
#define MAT_T    (128 * LDA * 2)
#define STAGE_B  (4 * MAT_T)
#define GEMM_SMEM (2 * STAGE_B)
#define LDC      132

__global__ __launch_bounds__(128) void gemm_bf16x3(
    const __nv_bfloat16* __restrict__ Ah, const __nv_bfloat16* __restrict__ Al,
    const __nv_bfloat16* __restrict__ Bh, const __nv_bfloat16* __restrict__ Bl,
    float* __restrict__ C, const float* __restrict__ bias,
    int M, int N, int K)
{
    extern __shared__ char smem[];
    const uint32_t sb = smem_u32(smem);
    const int tid = threadIdx.x;
    const int wid = tid >> 5;
    const int lane = tid & 31;
    const int wm = wid >> 1;
    const int wn = wid & 1;
    const int m0 = blockIdx.y * 128;
    const int n0 = blockIdx.x * 128;
    const int NK = K / BK;

    uint32_t doff[4];
    size_t goffA[4], goffB[4];
    #pragma unroll
    for (int it = 0; it < 4; it++) {
        const int id  = it * 128 + tid;
        const int row = id >> 2;
        const int seg = (id & 3) * 16;
        doff[it]  = row * (LDA * 2) + seg;
        goffA[it] = ((size_t)(m0 + row) * K) * 2 + seg;
        goffB[it] = ((size_t)(n0 + row) * K) * 2 + seg;
    }

    auto load_stage = [&](int s, int kc) {
        const uint32_t base = sb + s * STAGE_B;
        const size_t kb = (size_t)kc * (BK * 2);
        #pragma unroll
        for (int it = 0; it < 4; it++) {
            cp16(base + 0 * MAT_T + doff[it], (const char*)Ah + goffA[it] + kb);
            cp16(base + 1 * MAT_T + doff[it], (const char*)Al + goffA[it] + kb);
            cp16(base + 2 * MAT_T + doff[it], (const char*)Bh + goffB[it] + kb);
            cp16(base + 3 * MAT_T + doff[it], (const char*)Bl + goffB[it] + kb);
        }
        asm volatile("cp.async.commit_group;" ::: "memory");
    };

    wmma::fragment<wmma::accumulator, 16, 16, 16, float> acc[4][4];
    #pragma unroll
    for (int i = 0; i < 4; i++)
        #pragma unroll
        for (int j = 0; j < 4; j++)
            wmma::fill_fragment(acc[i][j], 0.0f);

    load_stage(0, 0);
    load_stage(1, 1);

    for (int kt = 0; kt < NK; kt++) {
        asm volatile("cp.async.wait_group 1;" ::: "memory");
        __syncthreads();

        const char* stg = smem + (kt & 1) * STAGE_B;
        const __nv_bfloat16* Ash_h = (const __nv_bfloat16*)(stg);
        const __nv_bfloat16* Ash_l = (const __nv_bfloat16*)(stg + MAT_T);
        const __nv_bfloat16* Bsh_h = (const __nv_bfloat16*)(stg + 2 * MAT_T);
        const __nv_bfloat16* Bsh_l = (const __nv_bfloat16*)(stg + 3 * MAT_T);

        #pragma unroll
        for (int ks = 0; ks < BK; ks += 16) {
            wmma::fragment<wmma::matrix_a, 16, 16, 16, __nv_bfloat16, wmma::row_major> ah[4], al[4];
            #pragma unroll
            for (int i = 0; i < 4; i++) {
                const int r = wm * 64 + i * 16;
                wmma::load_matrix_sync(ah[i], Ash_h + r * LDA + ks, LDA);
                wmma::load_matrix_sync(al[i], Ash_l + r * LDA + ks, LDA);
            }
            #pragma unroll
            for (int j = 0; j < 4; j++) {
                wmma::fragment<wmma::matrix_b, 16, 16, 16, __nv_bfloat16, wmma::col_major> bh, bl;
                const int c = wn * 64 + j * 16;
                wmma::load_matrix_sync(bh, Bsh_h + c * LDA + ks, LDA);
                wmma::load_matrix_sync(bl, Bsh_l + c * LDA + ks, LDA);
                #pragma unroll
                for (int i = 0; i < 4; i++) {
                    wmma::mma_sync(acc[i][j], ah[i], bh, acc[i][j]);
                    wmma::mma_sync(acc[i][j], ah[i], bl, acc[i][j]);
                    wmma::mma_sync(acc[i][j], al[i], bh, acc[i][j]);
                }
            }
        }

        __syncthreads();
        if (kt + 2 < NK) load_stage(kt & 1, kt + 2);
        else asm volatile("cp.async.commit_group;" ::: "memory");
    }

    if (!bias) {
        // direct global stores: warp slab rows m0+wm*64.., cols n0+wn*64..
        #pragma unroll
        for (int i = 0; i < 4; i++)
            #pragma unroll
            for (int j = 0; j < 4; j++)
                wmma::store_matrix_sync(
                    C + (size_t)(m0 + wm * 64 + i * 16) * N + n0 + wn * 64 + j * 16,
                    acc[i][j], N, wmma::mem_row_major);
        return;
    }

    // bias path: smem round-trip + coalesced stores
    __syncthreads();
    float* Csh = (float*)smem;
    #pragma unroll
    for (int i = 0; i < 4; i++)
        #pragma unroll
        for (int j = 0; j < 4; j++)
            wmma::store_matrix_sync(
                Csh + (wm * 64 + i * 16) * LDC + wn * 64 + j * 16,
                acc[i][j], LDC, wmma::mem_row_major);
    __syncthreads();

    float4 bb = *(const float4*)(bias + n0 + lane * 4);
    #pragma unroll 4
    for (int i = 0; i < 32; i++) {
        const int r = wid * 32 + i;
        float4 v = *(const float4*)(Csh + r * LDC + lane * 4);
        v.x += bb.x; v.y += bb.y; v.z += bb.z; v.w += bb.w;
        *(float4*)(C + (size_t)(m0 + r) * N + n0 + lane * 4) = v;
    }
}

// ---------------------------------------------------------------------------
// Fused attention (SIMT, round-5 design): one block per (b,h), thread per
// query row, single pass (logits bounded ~|8|, no max subtraction in fp32).
// Emits bf16 hi/lo directly for the projection GEMM.
// ---------------------------------------------------------------------------
#define ATT_THREADS 224
#define ATT_SMEM    ((2 * NSEQ * HDIM + 729) * (int)sizeof(float))   // 53092 B

__global__ __launch_bounds__(ATT_THREADS) void attention_kernel(
    const float* __restrict__ qkv,       // [12544, 3072]
    const float* __restrict__ rpk,       // [729, 32]
    __nv_bfloat16* __restrict__ ath,     // [12544, 1024]
    __nv_bfloat16* __restrict__ atl)
{
    extern __shared__ float smf[];
    float* Ksh = smf;
    float* Vsh = smf + NSEQ * HDIM;
    float* rsh = smf + 2 * NSEQ * HDIM;

    const int h   = blockIdx.x;
    const int b   = blockIdx.y;
    const int tid = threadIdx.x;

    const float* base = qkv + (size_t)b * NSEQ * QKVN + h * HDIM;

    for (int f = tid; f < NSEQ * 8; f += ATT_THREADS) {
        const int j  = f >> 3;
        const int d4 = (f & 7) * 4;
        const size_t row = (size_t)j * QKVN;
        *(float4*)(Ksh + j * HDIM + d4) = *(const float4*)(base + row + CDIM   + d4);
        *(float4*)(Vsh + j * HDIM + d4) = *(const float4*)(base + row + 2*CDIM + d4);
    }
    for (int i = tid; i < 729; i += ATT_THREADS)
        rsh[i] = rpk[(size_t)i * HDIM + h];
    __syncthreads();

    if (tid < NSEQ) {
        const int r = tid;
        const float scale = 0.17677669529663687f;

        float q[HDIM];
        #pragma unroll
        for (int d4 = 0; d4 < 8; d4++) {
            const float4 qv = *(const float4*)(base + (size_t)r * QKVN + d4 * 4);
            q[d4*4+0] = qv.x * scale;
            q[d4*4+1] = qv.y * scale;
            q[d4*4+2] = qv.z * scale;
            q[d4*4+3] = qv.w * scale;
        }

        float acc[HDIM];
        #pragma unroll
        for (int d = 0; d < HDIM; d++) acc[d] = 0.0f;
        float denom = 0.0f;

        const int dyc = (r / 14 + 13) * 27 + (r % 14) + 13;
        int t = 0, xj = 0;

        #pragma unroll 2
        for (int j = 0; j < NSEQ; j++) {
            const float* kj = Ksh + j * HDIM;
            float s0 = 0.f, s1 = 0.f, s2 = 0.f, s3 = 0.f;
            #pragma unroll
            for (int d4 = 0; d4 < 8; d4++) {
                const float4 kv = *(const float4*)(kj + d4 * 4);
                s0 = fmaf(q[d4*4+0], kv.x, s0);
                s1 = fmaf(q[d4*4+1], kv.y, s1);
                s2 = fmaf(q[d4*4+2], kv.z, s2);
                s3 = fmaf(q[d4*4+3], kv.w, s3);
            }
            const float logit = (s0 + s1) + (s2 + s3) + rsh[dyc - t];
            const float p = __expf(logit);
            denom += p;

            const float* vj = Vsh + j * HDIM;
            #pragma unroll
            for (int d4 = 0; d4 < 8; d4++) {
                const float4 vv = *(const float4*)(vj + d4 * 4);
                acc[d4*4+0] = fmaf(p, vv.x, acc[d4*4+0]);
                acc[d4*4+1] = fmaf(p, vv.y, acc[d4*4+1]);
                acc[d4*4+2] = fmaf(p, vv.z, acc[d4*4+2]);
                acc[d4*4+3] = fmaf(p, vv.w, acc[d4*4+3]);
            }
            t++;
            if (++xj == 14) { xj = 0; t += 13; }
        }

        const float inv = 1.0f / denom;
        __nv_bfloat16* oh = ath + (size_t)(b * NSEQ + r) * CDIM + h * HDIM;
        __nv_bfloat16* ol = atl + (size_t)(b * NSEQ + r) * CDIM + h * HDIM;
        #pragma unroll
        for (int d = 0; d < HDIM; d += 2) {
            const float o0 = acc[d]     * inv;
            const float o1 = acc[d + 1] * inv;
            const __nv_bfloat16 h0 = __float2bfloat16(o0);
            const __nv_bfloat16 h1 = __float2bfloat16(o1);
            *(__nv_bfloat162*)(oh + d) = __nv_bfloat162(h0, h1);
            *(__nv_bfloat162*)(ol + d) = __nv_bfloat162(
                __float2bfloat16(o0 - __bfloat162float(h0)),
                __float2bfloat16(o1 - __bfloat162float(h1)));
        }
    }
}

// ---------------------------------------------------------------------------
// Launch
// ---------------------------------------------------------------------------
extern "C" void kernel_launch(void* const* d_in, const int* in_sizes, int n_in,
                              void* d_out, int out_size)
{
    const float* x      = (const float*)d_in[0];
    const float* W_qkv  = (const float*)d_in[1];
    const float* W_proj = (const float*)d_in[2];
    const float* b_proj = (const float*)d_in[3];
    const float* rpk    = (const float*)d_in[4];
    float* out = (float*)d_out;

    float *qkv;
    __nv_bfloat16 *xh, *xl, *wqh, *wql, *wph, *wpl, *ath, *atl;
    cudaGetSymbolAddress((void**)&qkv, g_qkv);
    cudaGetSymbolAddress((void**)&xh,  g_xh);
    cudaGetSymbolAddress((void**)&xl,  g_xl);
    cudaGetSymbolAddress((void**)&wqh, g_wqh);
    cudaGetSymbolAddress((void**)&wql, g_wql);
    cudaGetSymbolAddress((void**)&wph, g_wph);
    cudaGetSymbolAddress((void**)&wpl, g_wpl);
    cudaGetSymbolAddress((void**)&ath, g_ath);
    cudaGetSymbolAddress((void**)&atl, g_atl);

    cudaFuncSetAttribute(gemm_bf16x3,
                         cudaFuncAttributeMaxDynamicSharedMemorySize, GEMM_SMEM);
    cudaFuncSetAttribute(attention_kernel,
                         cudaFuncAttributeMaxDynamicSharedMemorySize, ATT_SMEM);

    // 0) conversions
    split4_kernel<<<MROWS * CDIM / 1024, 256>>>(x, xh, xl);
    transpose_split_kernel<<<dim3(QKVN / 32, CDIM / 32), dim3(32, 8)>>>(
        W_qkv, wqh, wql, CDIM, QKVN);
    transpose_split_kernel<<<dim3(CDIM / 32, CDIM / 32), dim3(32, 8)>>>(
        W_proj, wph, wpl, CDIM, CDIM);

    // 1) QKV projection: [12544,1024] x [1024,3072]
    gemm_bf16x3<<<dim3(QKVN / 128, MROWS / 128), 128, GEMM_SMEM>>>(
        xh, xl, wqh, wql, qkv, nullptr, MROWS, QKVN, CDIM);

    // 2) SIMT attention per (b,h); writes bf16 hi/lo directly
    attention_kernel<<<dim3(NHEAD, BATCH), ATT_THREADS, ATT_SMEM>>>(qkv, rpk, ath, atl);

    // 3) output projection: [12544,1024] x [1024,1024] + bias
    gemm_bf16x3<<<dim3(CDIM / 128, MROWS / 128), 128, GEMM_SMEM>>>(
        ath, atl, wph, wpl, out, b_proj, MROWS, CDIM, CDIM);
}

// round 8
// speedup vs baseline: 1.4858x; 1.0545x over previous
#include <cuda_runtime.h>
#include <cuda_bf16.h>
#include <mma.h>
#include <stdint.h>
#include <math.h>

using namespace nvcuda;

// Problem constants
#define BATCH   64
#define NSEQ    196
#define CDIM    1024
#define NHEAD   32
#define HDIM    32
#define MROWS   12544            // BATCH*NSEQ
#define QKVN    3072             // 3*CDIM

// ---------------------------------------------------------------------------
// Static scratch (no cudaMalloc allowed)
// ---------------------------------------------------------------------------
__device__ float g_qkv[(size_t)MROWS * QKVN];       // [12544, 3072] fp32
__device__ __nv_bfloat16 g_xh[(size_t)MROWS * CDIM];
__device__ __nv_bfloat16 g_xl[(size_t)MROWS * CDIM];
__device__ __nv_bfloat16 g_wqh[(size_t)QKVN * CDIM];   // W_qkv^T [3072,1024]
__device__ __nv_bfloat16 g_wql[(size_t)QKVN * CDIM];
__device__ __nv_bfloat16 g_wph[(size_t)CDIM * CDIM];   // W_proj^T [1024,1024]
__device__ __nv_bfloat16 g_wpl[(size_t)CDIM * CDIM];
__device__ __nv_bfloat16 g_ath[(size_t)MROWS * CDIM];  // attention out hi
__device__ __nv_bfloat16 g_atl[(size_t)MROWS * CDIM];  // attention out lo

// ---------------------------------------------------------------------------
// helpers
// ---------------------------------------------------------------------------
__device__ __forceinline__ uint32_t smem_u32(const void* p) {
    uint32_t a;
    asm("{ .reg .u64 t; cvta.to.shared.u64 t, %1; cvt.u32.u64 %0, t; }"
        : "=r"(a) : "l"(p));
    return a;
}
__device__ __forceinline__ void cp16(uint32_t dst, const void* src) {
    asm volatile("cp.async.cg.shared.global [%0], [%1], 16;\n"
                 :: "r"(dst), "l"(src));
}

// packed f32x2 (PTX ISA 8.6, sm_100+ family-common)
__device__ __forceinline__ unsigned long long fma2(
    unsigned long long a, unsigned long long b, unsigned long long c) {
    unsigned long long d;
    asm("fma.rn.f32x2 %0, %1, %2, %3;" : "=l"(d) : "l"(a), "l"(b), "l"(c));
    return d;
}
__device__ __forceinline__ unsigned long long pack2(float x, float y) {
    unsigned long long r;
    asm("mov.b64 %0, {%1, %2};" : "=l"(r) : "f"(x), "f"(y));
    return r;
}
__device__ __forceinline__ float2 unpack2(unsigned long long v) {
    float2 r;
    asm("mov.b64 {%0, %1}, %2;" : "=f"(r.x), "=f"(r.y) : "l"(v));
    return r;
}

// ---------------------------------------------------------------------------
// bf16-split conversion kernels
// ---------------------------------------------------------------------------
__global__ __launch_bounds__(256) void split4_kernel(
    const float* __restrict__ in, __nv_bfloat16* __restrict__ hi,
    __nv_bfloat16* __restrict__ lo)
{
    const size_t i0 = ((size_t)blockIdx.x * 256 + threadIdx.x) * 4;
    const float4 v = *(const float4*)(in + i0);
    __nv_bfloat16 h0 = __float2bfloat16(v.x), h1 = __float2bfloat16(v.y);
    __nv_bfloat16 h2 = __float2bfloat16(v.z), h3 = __float2bfloat16(v.w);
    __nv_bfloat16 l0 = __float2bfloat16(v.x - __bfloat162float(h0));
    __nv_bfloat16 l1 = __float2bfloat16(v.y - __bfloat162float(h1));
    __nv_bfloat16 l2 = __float2bfloat16(v.z - __bfloat162float(h2));
    __nv_bfloat16 l3 = __float2bfloat16(v.w - __bfloat162float(h3));
    *(__nv_bfloat162*)(hi + i0)     = __nv_bfloat162(h0, h1);
    *(__nv_bfloat162*)(hi + i0 + 2) = __nv_bfloat162(h2, h3);
    *(__nv_bfloat162*)(lo + i0)     = __nv_bfloat162(l0, l1);
    *(__nv_bfloat162*)(lo + i0 + 2) = __nv_bfloat162(l2, l3);
}

// in: [K, N] fp32 row-major  ->  hi/lo: [N, K] bf16 row-major
__global__ __launch_bounds__(256) void transpose_split_kernel(
    const float* __restrict__ in, __nv_bfloat16* __restrict__ hi,
    __nv_bfloat16* __restrict__ lo, int K, int N)
{
    __shared__ float t[32][33];
    const int bx = blockIdx.x;   // tile over N
    const int by = blockIdx.y;   // tile over K
    const int x = bx * 32 + threadIdx.x;
    #pragma unroll
    for (int i = 0; i < 32; i += 8) {
        const int y = by * 32 + threadIdx.y + i;
        t[threadIdx.y + i][threadIdx.x] = in[(size_t)y * N + x];
    }
    __syncthreads();
    const int k = by * 32 + threadIdx.x;
    #pragma unroll
    for (int i = 0; i < 32; i += 8) {
        const int n = bx * 32 + threadIdx.y + i;
        const float v = t[threadIdx.x][threadIdx.y + i];
        const __nv_bfloat16 h = __float2bfloat16(v);
        hi[(size_t)n * K + k] = h;
        lo[(size_t)n * K + k] = __float2bfloat16(v - __bfloat162float(h));
    }
}

// ---------------------------------------------------------------------------
// HMMA bf16-split GEMM: C[M,N] = A*B^T (+bias).
// 128x128 CTA tile, BK=32, 4 warps (2x2), warp tile 64x64.
// Epilogue: smem round-trip + coalesced float4 stores (round-5 proven path).
// ---------------------------------------------------------------------------
#define BK       32
#define LDA      40
#define MAT_T    (128 * LDA * 2)
#define STAGE_B  (4 * MAT_T)
#define GEMM_SMEM (2 * STAGE_B)
#define LDC      132

__global__ __launch_bounds__(128) void gemm_bf16x3(
    const __nv_bfloat16* __restrict__ Ah, const __nv_bfloat16* __restrict__ Al,
    const __nv_bfloat16* __restrict__ Bh, const __nv_bfloat16* __restrict__ Bl,
    float* __restrict__ C, const float* __restrict__ bias,
    int M, int N, int K)
{
    extern __shared__ char smem[];
    const uint32_t sb = smem_u32(smem);
    const int tid = threadIdx.x;
    const int wid = tid >> 5;
    const int lane = tid & 31;
    const int wm = wid >> 1;
    const int wn = wid & 1;
    const int m0 = blockIdx.y * 128;
    const int n0 = blockIdx.x * 128;
    const int NK = K / BK;

    uint32_t doff[4];
    size_t goffA[4], goffB[4];
    #pragma unroll
    for (int it = 0; it < 4; it++) {
        const int id  = it * 128 + tid;
        const int row = id >> 2;
        const int seg = (id & 3) * 16;
        doff[it]  = row * (LDA * 2) + seg;
        goffA[it] = ((size_t)(m0 + row) * K) * 2 + seg;
        goffB[it] = ((size_t)(n0 + row) * K) * 2 + seg;
    }

    auto load_stage = [&](int s, int kc) {
        const uint32_t base = sb + s * STAGE_B;
        const size_t kb = (size_t)kc * (BK * 2);
        #pragma unroll
        for (int it = 0; it < 4; it++) {
            cp16(base + 0 * MAT_T + doff[it], (const char*)Ah + goffA[it] + kb);
            cp16(base + 1 * MAT_T + doff[it], (const char*)Al + goffA[it] + kb);
            cp16(base + 2 * MAT_T + doff[it], (const char*)Bh + goffB[it] + kb);
            cp16(base + 3 * MAT_T + doff[it], (const char*)Bl + goffB[it] + kb);
        }
        asm volatile("cp.async.commit_group;" ::: "memory");
    };

    wmma::fragment<wmma::accumulator, 16, 16, 16, float> acc[4][4];
    #pragma unroll
    for (int i = 0; i < 4; i++)
        #pragma unroll
        for (int j = 0; j < 4; j++)
            wmma::fill_fragment(acc[i][j], 0.0f);

    load_stage(0, 0);
    load_stage(1, 1);

    for (int kt = 0; kt < NK; kt++) {
        asm volatile("cp.async.wait_group 1;" ::: "memory");
        __syncthreads();

        const char* stg = smem + (kt & 1) * STAGE_B;
        const __nv_bfloat16* Ash_h = (const __nv_bfloat16*)(stg);
        const __nv_bfloat16* Ash_l = (const __nv_bfloat16*)(stg + MAT_T);
        const __nv_bfloat16* Bsh_h = (const __nv_bfloat16*)(stg + 2 * MAT_T);
        const __nv_bfloat16* Bsh_l = (const __nv_bfloat16*)(stg + 3 * MAT_T);

        #pragma unroll
        for (int ks = 0; ks < BK; ks += 16) {
            wmma::fragment<wmma::matrix_a, 16, 16, 16, __nv_bfloat16, wmma::row_major> ah[4], al[4];
            #pragma unroll
            for (int i = 0; i < 4; i++) {
                const int r = wm * 64 + i * 16;
                wmma::load_matrix_sync(ah[i], Ash_h + r * LDA + ks, LDA);
                wmma::load_matrix_sync(al[i], Ash_l + r * LDA + ks, LDA);
            }
            #pragma unroll
            for (int j = 0; j < 4; j++) {
                wmma::fragment<wmma::matrix_b, 16, 16, 16, __nv_bfloat16, wmma::col_major> bh, bl;
                const int c = wn * 64 + j * 16;
                wmma::load_matrix_sync(bh, Bsh_h + c * LDA + ks, LDA);
                wmma::load_matrix_sync(bl, Bsh_l + c * LDA + ks, LDA);
                #pragma unroll
                for (int i = 0; i < 4; i++) {
                    wmma::mma_sync(acc[i][j], ah[i], bh, acc[i][j]);
                    wmma::mma_sync(acc[i][j], ah[i], bl, acc[i][j]);
                    wmma::mma_sync(acc[i][j], al[i], bh, acc[i][j]);
                }
            }
        }

        __syncthreads();
        if (kt + 2 < NK) load_stage(kt & 1, kt + 2);
        else asm volatile("cp.async.commit_group;" ::: "memory");
    }

    // epilogue: frags -> smem (fp32, LDC=132), then bias add + coalesced store
    __syncthreads();
    float* Csh = (float*)smem;
    #pragma unroll
    for (int i = 0; i < 4; i++)
        #pragma unroll
        for (int j = 0; j < 4; j++)
            wmma::store_matrix_sync(
                Csh + (wm * 64 + i * 16) * LDC + wn * 64 + j * 16,
                acc[i][j], LDC, wmma::mem_row_major);
    __syncthreads();

    float4 bb = make_float4(0.f, 0.f, 0.f, 0.f);
    if (bias) bb = *(const float4*)(bias + n0 + lane * 4);
    #pragma unroll 4
    for (int i = 0; i < 32; i++) {
        const int r = wid * 32 + i;
        float4 v = *(const float4*)(Csh + r * LDC + lane * 4);
        v.x += bb.x; v.y += bb.y; v.z += bb.z; v.w += bb.w;
        *(float4*)(C + (size_t)(m0 + r) * N + n0 + lane * 4) = v;
    }
}

// ---------------------------------------------------------------------------
// Fused attention (SIMT + packed f32x2): one block per (b,h), thread per
// query row, single pass.  QK and PV inner loops use fma.rn.f32x2 (2 MACs
// per issued fma).  Emits bf16 hi/lo directly for the projection GEMM.
// ---------------------------------------------------------------------------
#define ATT_THREADS 224
#define ATT_SMEM    ((2 * NSEQ * HDIM + 729) * (int)sizeof(float))   // 53092 B

__global__ __launch_bounds__(ATT_THREADS) void attention_kernel(
    const float* __restrict__ qkv,       // [12544, 3072]
    const float* __restrict__ rpk,       // [729, 32]
    __nv_bfloat16* __restrict__ ath,     // [12544, 1024]
    __nv_bfloat16* __restrict__ atl)
{
    extern __shared__ float smf[];
    float* Ksh = smf;
    float* Vsh = smf + NSEQ * HDIM;
    float* rsh = smf + 2 * NSEQ * HDIM;

    const int h   = blockIdx.x;
    const int b   = blockIdx.y;
    const int tid = threadIdx.x;

    const float* base = qkv + (size_t)b * NSEQ * QKVN + h * HDIM;

    for (int f = tid; f < NSEQ * 8; f += ATT_THREADS) {
        const int j  = f >> 3;
        const int d4 = (f & 7) * 4;
        const size_t row = (size_t)j * QKVN;
        *(float4*)(Ksh + j * HDIM + d4) = *(const float4*)(base + row + CDIM   + d4);
        *(float4*)(Vsh + j * HDIM + d4) = *(const float4*)(base + row + 2*CDIM + d4);
    }
    for (int i = tid; i < 729; i += ATT_THREADS)
        rsh[i] = rpk[(size_t)i * HDIM + h];
    __syncthreads();

    if (tid < NSEQ) {
        const int r = tid;
        const float scale = 0.17677669529663687f;

        // load Q row, scale, pack into 16 f32x2 pairs
        unsigned long long q2[16];
        #pragma unroll
        for (int d4 = 0; d4 < 8; d4++) {
            const float4 qv = *(const float4*)(base + (size_t)r * QKVN + d4 * 4);
            q2[d4 * 2 + 0] = pack2(qv.x * scale, qv.y * scale);
            q2[d4 * 2 + 1] = pack2(qv.z * scale, qv.w * scale);
        }

        unsigned long long acc2[16];
        #pragma unroll
        for (int i = 0; i < 16; i++) acc2[i] = 0ull;
        float denom = 0.0f;

        const int dyc = (r / 14 + 13) * 27 + (r % 14) + 13;
        int t = 0, xj = 0;

        #pragma unroll 2
        for (int j = 0; j < NSEQ; j++) {
            const unsigned long long* kp =
                (const unsigned long long*)(Ksh + j * HDIM);
            unsigned long long s0 = 0ull, s1 = 0ull, s2 = 0ull, s3 = 0ull;
            #pragma unroll
            for (int i = 0; i < 16; i += 4) {
                s0 = fma2(q2[i + 0], kp[i + 0], s0);
                s1 = fma2(q2[i + 1], kp[i + 1], s1);
                s2 = fma2(q2[i + 2], kp[i + 2], s2);
                s3 = fma2(q2[i + 3], kp[i + 3], s3);
            }
            const float2 a = unpack2(s0), bb2 = unpack2(s1);
            const float2 c = unpack2(s2), d = unpack2(s3);
            const float s = ((a.x + a.y) + (bb2.x + bb2.y))
                          + ((c.x + c.y) + (d.x + d.y));
            const float p = __expf(s + rsh[dyc - t]);
            denom += p;
            const unsigned long long pp = pack2(p, p);

            const unsigned long long* vp =
                (const unsigned long long*)(Vsh + j * HDIM);
            #pragma unroll
            for (int i = 0; i < 16; i++)
                acc2[i] = fma2(pp, vp[i], acc2[i]);

            t++;
            if (++xj == 14) { xj = 0; t += 13; }
        }

        const float inv = 1.0f / denom;
        __nv_bfloat16* oh = ath + (size_t)(b * NSEQ + r) * CDIM + h * HDIM;
        __nv_bfloat16* ol = atl + (size_t)(b * NSEQ + r) * CDIM + h * HDIM;
        #pragma unroll
        for (int i = 0; i < 16; i++) {
            const float2 o = unpack2(acc2[i]);
            const float o0 = o.x * inv;
            const float o1 = o.y * inv;
            const __nv_bfloat16 h0 = __float2bfloat16(o0);
            const __nv_bfloat16 h1 = __float2bfloat16(o1);
            *(__nv_bfloat162*)(oh + i * 2) = __nv_bfloat162(h0, h1);
            *(__nv_bfloat162*)(ol + i * 2) = __nv_bfloat162(
                __float2bfloat16(o0 - __bfloat162float(h0)),
                __float2bfloat16(o1 - __bfloat162float(h1)));
        }
    }
}

// ---------------------------------------------------------------------------
// Launch
// ---------------------------------------------------------------------------
extern "C" void kernel_launch(void* const* d_in, const int* in_sizes, int n_in,
                              void* d_out, int out_size)
{
    const float* x      = (const float*)d_in[0];
    const float* W_qkv  = (const float*)d_in[1];
    const float* W_proj = (const float*)d_in[2];
    const float* b_proj = (const float*)d_in[3];
    const float* rpk    = (const float*)d_in[4];
    float* out = (float*)d_out;

    float *qkv;
    __nv_bfloat16 *xh, *xl, *wqh, *wql, *wph, *wpl, *ath, *atl;
    cudaGetSymbolAddress((void**)&qkv, g_qkv);
    cudaGetSymbolAddress((void**)&xh,  g_xh);
    cudaGetSymbolAddress((void**)&xl,  g_xl);
    cudaGetSymbolAddress((void**)&wqh, g_wqh);
    cudaGetSymbolAddress((void**)&wql, g_wql);
    cudaGetSymbolAddress((void**)&wph, g_wph);
    cudaGetSymbolAddress((void**)&wpl, g_wpl);
    cudaGetSymbolAddress((void**)&ath, g_ath);
    cudaGetSymbolAddress((void**)&atl, g_atl);

    cudaFuncSetAttribute(gemm_bf16x3,
                         cudaFuncAttributeMaxDynamicSharedMemorySize, GEMM_SMEM);
    cudaFuncSetAttribute(attention_kernel,
                         cudaFuncAttributeMaxDynamicSharedMemorySize, ATT_SMEM);

    // 0) conversions
    split4_kernel<<<MROWS * CDIM / 1024, 256>>>(x, xh, xl);
    transpose_split_kernel<<<dim3(QKVN / 32, CDIM / 32), dim3(32, 8)>>>(
        W_qkv, wqh, wql, CDIM, QKVN);
    transpose_split_kernel<<<dim3(CDIM / 32, CDIM / 32), dim3(32, 8)>>>(
        W_proj, wph, wpl, CDIM, CDIM);

    // 1) QKV projection: [12544,1024] x [1024,3072]
    gemm_bf16x3<<<dim3(QKVN / 128, MROWS / 128), 128, GEMM_SMEM>>>(
        xh, xl, wqh, wql, qkv, nullptr, MROWS, QKVN, CDIM);

    // 2) SIMT f32x2 attention per (b,h); writes bf16 hi/lo directly
    attention_kernel<<<dim3(NHEAD, BATCH), ATT_THREADS, ATT_SMEM>>>(qkv, rpk, ath, atl);

    // 3) output projection: [12544,1024] x [1024,1024] + bias
    gemm_bf16x3<<<dim3(CDIM / 128, MROWS / 128), 128, GEMM_SMEM>>>(
        ath, atl, wph, wpl, out, b_proj, MROWS, CDIM, CDIM);
}

// round 9
// speedup vs baseline: 1.7551x; 1.1813x over previous
#include <cuda_runtime.h>
#include <cuda_fp16.h>
#include <mma.h>
#include <stdint.h>
#include <math.h>

using namespace nvcuda;

// Problem constants
#define BATCH   64
#define NSEQ    196
#define CDIM    1024
#define NHEAD   32
#define HDIM    32
#define MROWS   12544            // BATCH*NSEQ
#define QKVN    3072             // 3*CDIM

// ---------------------------------------------------------------------------
// Static scratch (no cudaMalloc allowed)
// ---------------------------------------------------------------------------
__device__ float g_qkv[(size_t)MROWS * QKVN];       // [12544, 3072] fp32
__device__ __half g_xh[(size_t)MROWS * CDIM];       // x in fp16
__device__ __half g_wqh[(size_t)QKVN * CDIM];       // W_qkv^T hi [3072,1024]
__device__ __half g_wql[(size_t)QKVN * CDIM];       // W_qkv^T lo
__device__ __half g_wph[(size_t)CDIM * CDIM];       // W_proj^T hi
__device__ __half g_wpl[(size_t)CDIM * CDIM];       // W_proj^T lo
__device__ __half g_ath[(size_t)MROWS * CDIM];      // attention out fp16

// ---------------------------------------------------------------------------
// helpers
// ---------------------------------------------------------------------------
__device__ __forceinline__ uint32_t smem_u32(const void* p) {
    uint32_t a;
    asm("{ .reg .u64 t; cvta.to.shared.u64 t, %1; cvt.u32.u64 %0, t; }"
        : "=r"(a) : "l"(p));
    return a;
}
__device__ __forceinline__ void cp16(uint32_t dst, const void* src) {
    asm volatile("cp.async.cg.shared.global [%0], [%1], 16;\n"
                 :: "r"(dst), "l"(src));
}

// packed f32x2 (PTX ISA, sm_100+ family-common)
__device__ __forceinline__ unsigned long long fma2(
    unsigned long long a, unsigned long long b, unsigned long long c) {
    unsigned long long d;
    asm("fma.rn.f32x2 %0, %1, %2, %3;" : "=l"(d) : "l"(a), "l"(b), "l"(c));
    return d;
}
__device__ __forceinline__ unsigned long long pack2(float x, float y) {
    unsigned long long r;
    asm("mov.b64 %0, {%1, %2};" : "=l"(r) : "f"(x), "f"(y));
    return r;
}
__device__ __forceinline__ float2 unpack2(unsigned long long v) {
    float2 r;
    asm("mov.b64 {%0, %1}, %2;" : "=f"(r.x), "=f"(r.y) : "l"(v));
    return r;
}

// ---------------------------------------------------------------------------
// conversion kernels
// ---------------------------------------------------------------------------
__global__ __launch_bounds__(256) void convert4_kernel(
    const float* __restrict__ in, __half* __restrict__ out)
{
    const size_t i0 = ((size_t)blockIdx.x * 256 + threadIdx.x) * 4;
    const float4 v = *(const float4*)(in + i0);
    *(__half2*)(out + i0)     = __halves2half2(__float2half(v.x), __float2half(v.y));
    *(__half2*)(out + i0 + 2) = __halves2half2(__float2half(v.z), __float2half(v.w));
}

// in: [K, N] fp32 row-major  ->  hi/lo: [N, K] fp16 row-major
__global__ __launch_bounds__(256) void transpose_split_kernel(
    const float* __restrict__ in, __half* __restrict__ hi,
    __half* __restrict__ lo, int K, int N)
{
    __shared__ float t[32][33];
    const int bx = blockIdx.x;   // tile over N
    const int by = blockIdx.y;   // tile over K
    const int x = bx * 32 + threadIdx.x;
    #pragma unroll
    for (int i = 0; i < 32; i += 8) {
        const int y = by * 32 + threadIdx.y + i;
        t[threadIdx.y + i][threadIdx.x] = in[(size_t)y * N + x];
    }
    __syncthreads();
    const int k = by * 32 + threadIdx.x;
    #pragma unroll
    for (int i = 0; i < 32; i += 8) {
        const int n = bx * 32 + threadIdx.y + i;
        const float v = t[threadIdx.x][threadIdx.y + i];
        const __half h = __float2half(v);
        hi[(size_t)n * K + k] = h;
        lo[(size_t)n * K + k] = __float2half(v - __half2float(h));
    }
}

// ---------------------------------------------------------------------------
// HMMA fp16 2-term GEMM: C[M,N] = A*(Bh+Bl)^T (+bias).
// A=[M,K] fp16 row-major, Bh/Bl=[N,K] fp16 row-major (weight hi/lo split).
// 128x128 CTA tile, BK=32, 4 warps (2x2), warp tile 64x64.
// 3-matrix stages (30KB) double-buffered; smem 67.6KB -> 3 CTAs/SM.
// ---------------------------------------------------------------------------
#define BK       32
#define LDA      40                          // fp16 leading dim (80 B)
#define MAT_T    (128 * LDA * 2)             // 10240 B per matrix tile
#define STAGE_B  (3 * MAT_T)                 // 30720 B (A, Bh, Bl)
#define LDC      132
#define GEMM_SMEM (128 * LDC * 4)            // 67584 B (> 2*STAGE_B = 61440)

__global__ __launch_bounds__(128) void gemm_fp16x2(
    const __half* __restrict__ A,
    const __half* __restrict__ Bh, const __half* __restrict__ Bl,
    float* __restrict__ C, const float* __restrict__ bias,
    int M, int N, int K)
{
    extern __shared__ char smem[];
    const uint32_t sb = smem_u32(smem);
    const int tid = threadIdx.x;
    const int wid = tid >> 5;
    const int lane = tid & 31;
    const int wm = wid >> 1;
    const int wn = wid & 1;
    const int m0 = blockIdx.y * 128;
    const int n0 = blockIdx.x * 128;
    const int NK = K / BK;

    uint32_t doff[4];
    size_t goffA[4], goffB[4];
    #pragma unroll
    for (int it = 0; it < 4; it++) {
        const int id  = it * 128 + tid;
        const int row = id >> 2;
        const int seg = (id & 3) * 16;
        doff[it]  = row * (LDA * 2) + seg;
        goffA[it] = ((size_t)(m0 + row) * K) * 2 + seg;
        goffB[it] = ((size_t)(n0 + row) * K) * 2 + seg;
    }

    auto load_stage = [&](int s, int kc) {
        const uint32_t base = sb + s * STAGE_B;
        const size_t kb = (size_t)kc * (BK * 2);
        #pragma unroll
        for (int it = 0; it < 4; it++) {
            cp16(base + 0 * MAT_T + doff[it], (const char*)A  + goffA[it] + kb);
            cp16(base + 1 * MAT_T + doff[it], (const char*)Bh + goffB[it] + kb);
            cp16(base + 2 * MAT_T + doff[it], (const char*)Bl + goffB[it] + kb);
        }
        asm volatile("cp.async.commit_group;" ::: "memory");
    };

    wmma::fragment<wmma::accumulator, 16, 16, 16, float> acc[4][4];
    #pragma unroll
    for (int i = 0; i < 4; i++)
        #pragma unroll
        for (int j = 0; j < 4; j++)
            wmma::fill_fragment(acc[i][j], 0.0f);

    load_stage(0, 0);
    load_stage(1, 1);

    for (int kt = 0; kt < NK; kt++) {
        asm volatile("cp.async.wait_group 1;" ::: "memory");
        __syncthreads();

        const char* stg = smem + (kt & 1) * STAGE_B;
        const __half* Ash   = (const __half*)(stg);
        const __half* Bsh_h = (const __half*)(stg + MAT_T);
        const __half* Bsh_l = (const __half*)(stg + 2 * MAT_T);

        #pragma unroll
        for (int ks = 0; ks < BK; ks += 16) {
            wmma::fragment<wmma::matrix_a, 16, 16, 16, __half, wmma::row_major> af[4];
            #pragma unroll
            for (int i = 0; i < 4; i++) {
                const int r = wm * 64 + i * 16;
                wmma::load_matrix_sync(af[i], Ash + r * LDA + ks, LDA);
            }
            #pragma unroll
            for (int j = 0; j < 4; j++) {
                wmma::fragment<wmma::matrix_b, 16, 16, 16, __half, wmma::col_major> bh, bl;
                const int c = wn * 64 + j * 16;
                wmma::load_matrix_sync(bh, Bsh_h + c * LDA + ks, LDA);
                wmma::load_matrix_sync(bl, Bsh_l + c * LDA + ks, LDA);
                #pragma unroll
                for (int i = 0; i < 4; i++) {
                    wmma::mma_sync(acc[i][j], af[i], bh, acc[i][j]);
                    wmma::mma_sync(acc[i][j], af[i], bl, acc[i][j]);
                }
            }
        }

        __syncthreads();
        if (kt + 2 < NK) load_stage(kt & 1, kt + 2);
        else asm volatile("cp.async.commit_group;" ::: "memory");
    }

    // epilogue: frags -> smem (fp32, LDC=132), then bias add + coalesced store
    __syncthreads();
    float* Csh = (float*)smem;
    #pragma unroll
    for (int i = 0; i < 4; i++)
        #pragma unroll
        for (int j = 0; j < 4; j++)
            wmma::store_matrix_sync(
                Csh + (wm * 64 + i * 16) * LDC + wn * 64 + j * 16,
                acc[i][j], LDC, wmma::mem_row_major);
    __syncthreads();

    float4 bb = make_float4(0.f, 0.f, 0.f, 0.f);
    if (bias) bb = *(const float4*)(bias + n0 + lane * 4);
    #pragma unroll 4
    for (int i = 0; i < 32; i++) {
        const int r = wid * 32 + i;
        float4 v = *(const float4*)(Csh + r * LDC + lane * 4);
        v.x += bb.x; v.y += bb.y; v.z += bb.z; v.w += bb.w;
        *(float4*)(C + (size_t)(m0 + r) * N + n0 + lane * 4) = v;
    }
}

// ---------------------------------------------------------------------------
// Fused attention (SIMT + packed f32x2): one block per (b,h), thread per
// query row, single pass.  Emits fp16 output directly for the proj GEMM.
// ---------------------------------------------------------------------------
#define ATT_THREADS 224
#define ATT_SMEM    ((2 * NSEQ * HDIM + 729) * (int)sizeof(float))   // 53092 B

__global__ __launch_bounds__(ATT_THREADS) void attention_kernel(
    const float* __restrict__ qkv,       // [12544, 3072]
    const float* __restrict__ rpk,       // [729, 32]
    __half* __restrict__ ath)            // [12544, 1024] fp16
{
    extern __shared__ float smf[];
    float* Ksh = smf;
    float* Vsh = smf + NSEQ * HDIM;
    float* rsh = smf + 2 * NSEQ * HDIM;

    const int h   = blockIdx.x;
    const int b   = blockIdx.y;
    const int tid = threadIdx.x;

    const float* base = qkv + (size_t)b * NSEQ * QKVN + h * HDIM;

    for (int f = tid; f < NSEQ * 8; f += ATT_THREADS) {
        const int j  = f >> 3;
        const int d4 = (f & 7) * 4;
        const size_t row = (size_t)j * QKVN;
        *(float4*)(Ksh + j * HDIM + d4) = *(const float4*)(base + row + CDIM   + d4);
        *(float4*)(Vsh + j * HDIM + d4) = *(const float4*)(base + row + 2*CDIM + d4);
    }
    for (int i = tid; i < 729; i += ATT_THREADS)
        rsh[i] = rpk[(size_t)i * HDIM + h];
    __syncthreads();

    if (tid < NSEQ) {
        const int r = tid;
        const float scale = 0.17677669529663687f;

        unsigned long long q2[16];
        #pragma unroll
        for (int d4 = 0; d4 < 8; d4++) {
            const float4 qv = *(const float4*)(base + (size_t)r * QKVN + d4 * 4);
            q2[d4 * 2 + 0] = pack2(qv.x * scale, qv.y * scale);
            q2[d4 * 2 + 1] = pack2(qv.z * scale, qv.w * scale);
        }

        unsigned long long acc2[16];
        #pragma unroll
        for (int i = 0; i < 16; i++) acc2[i] = 0ull;
        float denom = 0.0f;

        const int dyc = (r / 14 + 13) * 27 + (r % 14) + 13;
        int t = 0, xj = 0;

        #pragma unroll 2
        for (int j = 0; j < NSEQ; j++) {
            const unsigned long long* kp =
                (const unsigned long long*)(Ksh + j * HDIM);
            unsigned long long s0 = 0ull, s1 = 0ull, s2 = 0ull, s3 = 0ull;
            #pragma unroll
            for (int i = 0; i < 16; i += 4) {
                s0 = fma2(q2[i + 0], kp[i + 0], s0);
                s1 = fma2(q2[i + 1], kp[i + 1], s1);
                s2 = fma2(q2[i + 2], kp[i + 2], s2);
                s3 = fma2(q2[i + 3], kp[i + 3], s3);
            }
            const float2 a = unpack2(s0), bb2 = unpack2(s1);
            const float2 c = unpack2(s2), d = unpack2(s3);
            const float s = ((a.x + a.y) + (bb2.x + bb2.y))
                          + ((c.x + c.y) + (d.x + d.y));
            const float p = __expf(s + rsh[dyc - t]);
            denom += p;
            const unsigned long long pp = pack2(p, p);

            const unsigned long long* vp =
                (const unsigned long long*)(Vsh + j * HDIM);
            #pragma unroll
            for (int i = 0; i < 16; i++)
                acc2[i] = fma2(pp, vp[i], acc2[i]);

            t++;
            if (++xj == 14) { xj = 0; t += 13; }
        }

        const float inv = 1.0f / denom;
        __half* oh = ath + (size_t)(b * NSEQ + r) * CDIM + h * HDIM;
        #pragma unroll
        for (int i = 0; i < 16; i++) {
            const float2 o = unpack2(acc2[i]);
            *(__half2*)(oh + i * 2) = __halves2half2(
                __float2half(o.x * inv), __float2half(o.y * inv));
        }
    }
}

// ---------------------------------------------------------------------------
// Launch
// ---------------------------------------------------------------------------
extern "C" void kernel_launch(void* const* d_in, const int* in_sizes, int n_in,
                              void* d_out, int out_size)
{
    const float* x      = (const float*)d_in[0];
    const float* W_qkv  = (const float*)d_in[1];
    const float* W_proj = (const float*)d_in[2];
    const float* b_proj = (const float*)d_in[3];
    const float* rpk    = (const float*)d_in[4];
    float* out = (float*)d_out;

    float *qkv;
    __half *xh, *wqh, *wql, *wph, *wpl, *ath;
    cudaGetSymbolAddress((void**)&qkv, g_qkv);
    cudaGetSymbolAddress((void**)&xh,  g_xh);
    cudaGetSymbolAddress((void**)&wqh, g_wqh);
    cudaGetSymbolAddress((void**)&wql, g_wql);
    cudaGetSymbolAddress((void**)&wph, g_wph);
    cudaGetSymbolAddress((void**)&wpl, g_wpl);
    cudaGetSymbolAddress((void**)&ath, g_ath);

    cudaFuncSetAttribute(gemm_fp16x2,
                         cudaFuncAttributeMaxDynamicSharedMemorySize, GEMM_SMEM);
    cudaFuncSetAttribute(attention_kernel,
                         cudaFuncAttributeMaxDynamicSharedMemorySize, ATT_SMEM);

    // 0) conversions
    convert4_kernel<<<MROWS * CDIM / 1024, 256>>>(x, xh);
    transpose_split_kernel<<<dim3(QKVN / 32, CDIM / 32), dim3(32, 8)>>>(
        W_qkv, wqh, wql, CDIM, QKVN);
    transpose_split_kernel<<<dim3(CDIM / 32, CDIM / 32), dim3(32, 8)>>>(
        W_proj, wph, wpl, CDIM, CDIM);

    // 1) QKV projection: [12544,1024] x [1024,3072]
    gemm_fp16x2<<<dim3(QKVN / 128, MROWS / 128), 128, GEMM_SMEM>>>(
        xh, wqh, wql, qkv, nullptr, MROWS, QKVN, CDIM);

    // 2) SIMT f32x2 attention per (b,h); writes fp16 directly
    attention_kernel<<<dim3(NHEAD, BATCH), ATT_THREADS, ATT_SMEM>>>(qkv, rpk, ath);

    // 3) output projection: [12544,1024] x [1024,1024] + bias
    gemm_fp16x2<<<dim3(CDIM / 128, MROWS / 128), 128, GEMM_SMEM>>>(
        ath, wph, wpl, out, b_proj, MROWS, CDIM, CDIM);
}

// round 10
// speedup vs baseline: 1.8228x; 1.0386x over previous
#include <cuda_runtime.h>
#include <cuda_fp16.h>
#include <mma.h>
#include <stdint.h>
#include <math.h>

using namespace nvcuda;

// Problem constants
#define BATCH   64
#define NSEQ    196
#define CDIM    1024
#define NHEAD   32
#define HDIM    32
#define MROWS   12544            // BATCH*NSEQ
#define QKVN    3072             // 3*CDIM

// ---------------------------------------------------------------------------
// Static scratch (no cudaMalloc allowed)
// ---------------------------------------------------------------------------
__device__ float g_qkv[(size_t)MROWS * QKVN];       // [12544, 3072] fp32
__device__ __half g_xh[(size_t)MROWS * CDIM];       // x in fp16
__device__ __half g_wqh[(size_t)QKVN * CDIM];       // W_qkv^T hi [3072,1024]
__device__ __half g_wql[(size_t)QKVN * CDIM];       // W_qkv^T lo
__device__ __half g_wph[(size_t)CDIM * CDIM];       // W_proj^T hi
__device__ __half g_wpl[(size_t)CDIM * CDIM];       // W_proj^T lo
__device__ __half g_ath[(size_t)MROWS * CDIM];      // attention out fp16

// ---------------------------------------------------------------------------
// helpers
// ---------------------------------------------------------------------------
__device__ __forceinline__ uint32_t smem_u32(const void* p) {
    uint32_t a;
    asm("{ .reg .u64 t; cvta.to.shared.u64 t, %1; cvt.u32.u64 %0, t; }"
        : "=r"(a) : "l"(p));
    return a;
}
__device__ __forceinline__ void cp16(uint32_t dst, const void* src) {
    asm volatile("cp.async.cg.shared.global [%0], [%1], 16;\n"
                 :: "r"(dst), "l"(src));
}

// packed f32x2 (PTX ISA, sm_100+ family-common)
__device__ __forceinline__ unsigned long long fma2(
    unsigned long long a, unsigned long long b, unsigned long long c) {
    unsigned long long d;
    asm("fma.rn.f32x2 %0, %1, %2, %3;" : "=l"(d) : "l"(a), "l"(b), "l"(c));
    return d;
}
__device__ __forceinline__ unsigned long long pack2(float x, float y) {
    unsigned long long r;
    asm("mov.b64 %0, {%1, %2};" : "=l"(r) : "f"(x), "f"(y));
    return r;
}
__device__ __forceinline__ float2 unpack2(unsigned long long v) {
    float2 r;
    asm("mov.b64 {%0, %1}, %2;" : "=f"(r.x), "=f"(r.y) : "l"(v));
    return r;
}

// ---------------------------------------------------------------------------
// conversion kernels
// ---------------------------------------------------------------------------
__global__ __launch_bounds__(256) void convert4_kernel(
    const float* __restrict__ in, __half* __restrict__ out)
{
    const size_t i0 = ((size_t)blockIdx.x * 256 + threadIdx.x) * 4;
    const float4 v = *(const float4*)(in + i0);
    *(__half2*)(out + i0)     = __halves2half2(__float2half(v.x), __float2half(v.y));
    *(__half2*)(out + i0 + 2) = __halves2half2(__float2half(v.z), __float2half(v.w));
}

// in: [K, N] fp32 row-major  ->  hi/lo: [N, K] fp16 row-major
__global__ __launch_bounds__(256) void transpose_split_kernel(
    const float* __restrict__ in, __half* __restrict__ hi,
    __half* __restrict__ lo, int K, int N)
{
    __shared__ float t[32][33];
    const int bx = blockIdx.x;   // tile over N
    const int by = blockIdx.y;   // tile over K
    const int x = bx * 32 + threadIdx.x;
    #pragma unroll
    for (int i = 0; i < 32; i += 8) {
        const int y = by * 32 + threadIdx.y + i;
        t[threadIdx.y + i][threadIdx.x] = in[(size_t)y * N + x];
    }
    __syncthreads();
    const int k = by * 32 + threadIdx.x;
    #pragma unroll
    for (int i = 0; i < 32; i += 8) {
        const int n = bx * 32 + threadIdx.y + i;
        const float v = t[threadIdx.x][threadIdx.y + i];
        const __half h = __float2half(v);
        hi[(size_t)n * K + k] = h;
        lo[(size_t)n * K + k] = __float2half(v - __half2float(h));
    }
}

// ---------------------------------------------------------------------------
// HMMA fp16 2-term GEMM: C[M,N] = A*(Bh+Bl)^T (+bias).
// A=[M,K] fp16 row-major, Bh/Bl=[N,K] fp16 row-major (weight hi/lo split).
// 128x128 CTA tile, BK=32, 4 warps (2x2), warp tile 64x64.
// __launch_bounds__(128,3): cap regs at 170 -> 3 CTAs/SM (12 warps).
// ---------------------------------------------------------------------------
#define BK       32
#define LDA      40                          // fp16 leading dim (80 B)
#define MAT_T    (128 * LDA * 2)             // 10240 B per matrix tile
#define STAGE_B  (3 * MAT_T)                 // 30720 B (A, Bh, Bl)
#define LDC      132
#define GEMM_SMEM (128 * LDC * 4)            // 67584 B (> 2*STAGE_B = 61440)

__global__ __launch_bounds__(128, 3) void gemm_fp16x2(
    const __half* __restrict__ A,
    const __half* __restrict__ Bh, const __half* __restrict__ Bl,
    float* __restrict__ C, const float* __restrict__ bias,
    int M, int N, int K)
{
    extern __shared__ char smem[];
    const uint32_t sb = smem_u32(smem);
    const int tid = threadIdx.x;
    const int wid = tid >> 5;
    const int lane = tid & 31;
    const int wm = wid >> 1;
    const int wn = wid & 1;
    const int m0 = blockIdx.y * 128;
    const int n0 = blockIdx.x * 128;
    const int NK = K / BK;

    uint32_t doff[4];
    size_t goffA[4], goffB[4];
    #pragma unroll
    for (int it = 0; it < 4; it++) {
        const int id  = it * 128 + tid;
        const int row = id >> 2;
        const int seg = (id & 3) * 16;
        doff[it]  = row * (LDA * 2) + seg;
        goffA[it] = ((size_t)(m0 + row) * K) * 2 + seg;
        goffB[it] = ((size_t)(n0 + row) * K) * 2 + seg;
    }

    auto load_stage = [&](int s, int kc) {
        const uint32_t base = sb + s * STAGE_B;
        const size_t kb = (size_t)kc * (BK * 2);
        #pragma unroll
        for (int it = 0; it < 4; it++) {
            cp16(base + 0 * MAT_T + doff[it], (const char*)A  + goffA[it] + kb);
            cp16(base + 1 * MAT_T + doff[it], (const char*)Bh + goffB[it] + kb);
            cp16(base + 2 * MAT_T + doff[it], (const char*)Bl + goffB[it] + kb);
        }
        asm volatile("cp.async.commit_group;" ::: "memory");
    };

    wmma::fragment<wmma::accumulator, 16, 16, 16, float> acc[4][4];
    #pragma unroll
    for (int i = 0; i < 4; i++)
        #pragma unroll
        for (int j = 0; j < 4; j++)
            wmma::fill_fragment(acc[i][j], 0.0f);

    load_stage(0, 0);
    load_stage(1, 1);

    for (int kt = 0; kt < NK; kt++) {
        asm volatile("cp.async.wait_group 1;" ::: "memory");
        __syncthreads();

        const char* stg = smem + (kt & 1) * STAGE_B;
        const __half* Ash   = (const __half*)(stg);
        const __half* Bsh_h = (const __half*)(stg + MAT_T);
        const __half* Bsh_l = (const __half*)(stg + 2 * MAT_T);

        #pragma unroll
        for (int ks = 0; ks < BK; ks += 16) {
            wmma::fragment<wmma::matrix_a, 16, 16, 16, __half, wmma::row_major> af[4];
            #pragma unroll
            for (int i = 0; i < 4; i++) {
                const int r = wm * 64 + i * 16;
                wmma::load_matrix_sync(af[i], Ash + r * LDA + ks, LDA);
            }
            #pragma unroll
            for (int j = 0; j < 4; j++) {
                wmma::fragment<wmma::matrix_b, 16, 16, 16, __half, wmma::col_major> bh, bl;
                const int c = wn * 64 + j * 16;
                wmma::load_matrix_sync(bh, Bsh_h + c * LDA + ks, LDA);
                wmma::load_matrix_sync(bl, Bsh_l + c * LDA + ks, LDA);
                #pragma unroll
                for (int i = 0; i < 4; i++) {
                    wmma::mma_sync(acc[i][j], af[i], bh, acc[i][j]);
                    wmma::mma_sync(acc[i][j], af[i], bl, acc[i][j]);
                }
            }
        }

        __syncthreads();
        if (kt + 2 < NK) load_stage(kt & 1, kt + 2);
        else asm volatile("cp.async.commit_group;" ::: "memory");
    }

    // epilogue: frags -> smem (fp32, LDC=132), then bias add + coalesced store
    __syncthreads();
    float* Csh = (float*)smem;
    #pragma unroll
    for (int i = 0; i < 4; i++)
        #pragma unroll
        for (int j = 0; j < 4; j++)
            wmma::store_matrix_sync(
                Csh + (wm * 64 + i * 16) * LDC + wn * 64 + j * 16,
                acc[i][j], LDC, wmma::mem_row_major);
    __syncthreads();

    float4 bb = make_float4(0.f, 0.f, 0.f, 0.f);
    if (bias) bb = *(const float4*)(bias + n0 + lane * 4);
    #pragma unroll 4
    for (int i = 0; i < 32; i++) {
        const int r = wid * 32 + i;
        float4 v = *(const float4*)(Csh + r * LDC + lane * 4);
        v.x += bb.x; v.y += bb.y; v.z += bb.z; v.w += bb.w;
        *(float4*)(C + (size_t)(m0 + r) * N + n0 + lane * 4) = v;
    }
}

// ---------------------------------------------------------------------------
// Fused attention (SIMT + packed f32x2, LDS.128 smem loads): one block per
// (b,h), thread per query row, single pass.  Emits fp16 output directly.
// ---------------------------------------------------------------------------
#define ATT_THREADS 224
#define ATT_SMEM    ((2 * NSEQ * HDIM + 729) * (int)sizeof(float))   // 53092 B

__global__ __launch_bounds__(ATT_THREADS) void attention_kernel(
    const float* __restrict__ qkv,       // [12544, 3072]
    const float* __restrict__ rpk,       // [729, 32]
    __half* __restrict__ ath)            // [12544, 1024] fp16
{
    extern __shared__ float smf[];
    float* Ksh = smf;
    float* Vsh = smf + NSEQ * HDIM;
    float* rsh = smf + 2 * NSEQ * HDIM;

    const int h   = blockIdx.x;
    const int b   = blockIdx.y;
    const int tid = threadIdx.x;

    const float* base = qkv + (size_t)b * NSEQ * QKVN + h * HDIM;

    for (int f = tid; f < NSEQ * 8; f += ATT_THREADS) {
        const int j  = f >> 3;
        const int d4 = (f & 7) * 4;
        const size_t row = (size_t)j * QKVN;
        *(float4*)(Ksh + j * HDIM + d4) = *(const float4*)(base + row + CDIM   + d4);
        *(float4*)(Vsh + j * HDIM + d4) = *(const float4*)(base + row + 2*CDIM + d4);
    }
    for (int i = tid; i < 729; i += ATT_THREADS)
        rsh[i] = rpk[(size_t)i * HDIM + h];
    __syncthreads();

    if (tid < NSEQ) {
        const int r = tid;
        const float scale = 0.17677669529663687f;

        unsigned long long q2[16];
        #pragma unroll
        for (int d4 = 0; d4 < 8; d4++) {
            const float4 qv = *(const float4*)(base + (size_t)r * QKVN + d4 * 4);
            q2[d4 * 2 + 0] = pack2(qv.x * scale, qv.y * scale);
            q2[d4 * 2 + 1] = pack2(qv.z * scale, qv.w * scale);
        }

        unsigned long long acc2[16];
        #pragma unroll
        for (int i = 0; i < 16; i++) acc2[i] = 0ull;
        float denom = 0.0f;

        const int dyc = (r / 14 + 13) * 27 + (r % 14) + 13;
        int t = 0, xj = 0;

        #pragma unroll 2
        for (int j = 0; j < NSEQ; j++) {
            const ulonglong2* kp = (const ulonglong2*)(Ksh + j * HDIM);
            unsigned long long s0 = 0ull, s1 = 0ull, s2 = 0ull, s3 = 0ull;
            #pragma unroll
            for (int i = 0; i < 8; i += 2) {
                const ulonglong2 k0 = kp[i];
                const ulonglong2 k1 = kp[i + 1];
                s0 = fma2(q2[2 * i + 0], k0.x, s0);
                s1 = fma2(q2[2 * i + 1], k0.y, s1);
                s2 = fma2(q2[2 * i + 2], k1.x, s2);
                s3 = fma2(q2[2 * i + 3], k1.y, s3);
            }
            const float2 a = unpack2(s0), bb2 = unpack2(s1);
            const float2 c = unpack2(s2), d = unpack2(s3);
            const float s = ((a.x + a.y) + (bb2.x + bb2.y))
                          + ((c.x + c.y) + (d.x + d.y));
            const float p = __expf(s + rsh[dyc - t]);
            denom += p;
            const unsigned long long pp = pack2(p, p);

            const ulonglong2* vp = (const ulonglong2*)(Vsh + j * HDIM);
            #pragma unroll
            for (int i = 0; i < 8; i++) {
                const ulonglong2 v = vp[i];
                acc2[2 * i + 0] = fma2(pp, v.x, acc2[2 * i + 0]);
                acc2[2 * i + 1] = fma2(pp, v.y, acc2[2 * i + 1]);
            }

            t++;
            if (++xj == 14) { xj = 0; t += 13; }
        }

        const float inv = 1.0f / denom;
        __half* oh = ath + (size_t)(b * NSEQ + r) * CDIM + h * HDIM;
        #pragma unroll
        for (int i = 0; i < 16; i++) {
            const float2 o = unpack2(acc2[i]);
            *(__half2*)(oh + i * 2) = __halves2half2(
                __float2half(o.x * inv), __float2half(o.y * inv));
        }
    }
}

// ---------------------------------------------------------------------------
// Launch
// ---------------------------------------------------------------------------
extern "C" void kernel_launch(void* const* d_in, const int* in_sizes, int n_in,
                              void* d_out, int out_size)
{
    const float* x      = (const float*)d_in[0];
    const float* W_qkv  = (const float*)d_in[1];
    const float* W_proj = (const float*)d_in[2];
    const float* b_proj = (const float*)d_in[3];
    const float* rpk    = (const float*)d_in[4];
    float* out = (float*)d_out;

    float *qkv;
    __half *xh, *wqh, *wql, *wph, *wpl, *ath;
    cudaGetSymbolAddress((void**)&qkv, g_qkv);
    cudaGetSymbolAddress((void**)&xh,  g_xh);
    cudaGetSymbolAddress((void**)&wqh, g_wqh);
    cudaGetSymbolAddress((void**)&wql, g_wql);
    cudaGetSymbolAddress((void**)&wph, g_wph);
    cudaGetSymbolAddress((void**)&wpl, g_wpl);
    cudaGetSymbolAddress((void**)&ath, g_ath);

    cudaFuncSetAttribute(gemm_fp16x2,
                         cudaFuncAttributeMaxDynamicSharedMemorySize, GEMM_SMEM);
    cudaFuncSetAttribute(attention_kernel,
                         cudaFuncAttributeMaxDynamicSharedMemorySize, ATT_SMEM);

    // 0) conversions
    convert4_kernel<<<MROWS * CDIM / 1024, 256>>>(x, xh);
    transpose_split_kernel<<<dim3(QKVN / 32, CDIM / 32), dim3(32, 8)>>>(
        W_qkv, wqh, wql, CDIM, QKVN);
    transpose_split_kernel<<<dim3(CDIM / 32, CDIM / 32), dim3(32, 8)>>>(
        W_proj, wph, wpl, CDIM, CDIM);

    // 1) QKV projection: [12544,1024] x [1024,3072]
    gemm_fp16x2<<<dim3(QKVN / 128, MROWS / 128), 128, GEMM_SMEM>>>(
        xh, wqh, wql, qkv, nullptr, MROWS, QKVN, CDIM);

    // 2) SIMT f32x2 attention per (b,h); writes fp16 directly
    attention_kernel<<<dim3(NHEAD, BATCH), ATT_THREADS, ATT_SMEM>>>(qkv, rpk, ath);

    // 3) output projection: [12544,1024] x [1024,1024] + bias
    gemm_fp16x2<<<dim3(CDIM / 128, MROWS / 128), 128, GEMM_SMEM>>>(
        ath, wph, wpl, out, b_proj, MROWS, CDIM, CDIM);
}